// round 2
// baseline (speedup 1.0000x reference)
#include <cuda_runtime.h>

#define N_OUT   100000
#define KBINS   9
#define C_IN    32
#define C_A     24
#define C_B     8
#define C_OUT   32
#define JTOT    (KBINS * C_IN)      // 288
#define JSLICE  (JTOT / 8)          // 36
#define GROUPS  (N_OUT / 8)         // 12500 (exact)
#define E_MAX   1600000

typedef unsigned long long ull;

// ---- f32x2 packed helpers (sm_100+) ---------------------------------------
__device__ __forceinline__ ull pack2(float x, float y) {
    ull r; asm("mov.b64 %0, {%1, %2};" : "=l"(r) : "f"(x), "f"(y)); return r;
}
__device__ __forceinline__ void unpack2(ull v, float &x, float &y) {
    asm("mov.b64 {%0, %1}, %2;" : "=f"(x), "=f"(y) : "l"(v));
}
__device__ __forceinline__ ull add2(ull a, ull b) {
    ull r; asm("add.rn.f32x2 %0, %1, %2;" : "=l"(r) : "l"(a), "l"(b)); return r;
}
__device__ __forceinline__ ull fma2(ull a, ull b, ull c) {
    ull r; asm("fma.rn.f32x2 %0, %1, %2, %3;" : "=l"(r) : "l"(a), "l"(b), "l"(c)); return r;
}

// ---- device scratch (no allocation allowed) --------------------------------
__device__ float g_Wt[JTOT][C_OUT];       // Wt[j][f], j = k*32+c
__device__ int   g_row_start[N_OUT + 1];  // CSR offsets
__device__ int2  g_edge[E_MAX];           // (ni | k<<18, bitcast importance)

// ---------------------------------------------------------------------------
__global__ void prep_wt_kernel(const float* __restrict__ W_a,
                               const float* __restrict__ W_b) {
    int idx = blockIdx.x * blockDim.x + threadIdx.x;
    if (idx >= JTOT * C_OUT) return;
    int j = idx / C_OUT, f = idx % C_OUT;
    int k = j / C_IN,  c = j % C_IN;
    float w = (f < C_A) ? W_a[(k * C_IN + c) * C_A + f]
                        : W_b[(k * C_IN + c) * C_B + (f - C_A)];
    g_Wt[j][f] = w;
}

__global__ void prep_rows_kernel(const int* __restrict__ out_idx, int E) {
    int n = blockIdx.x * blockDim.x + threadIdx.x;
    if (n > N_OUT) return;
    int lo = 0, hi = E;
    while (lo < hi) {
        int mid = (lo + hi) >> 1;
        if (out_idx[mid] < n) lo = mid + 1; else hi = mid;
    }
    g_row_start[n] = lo;
}

__global__ void prep_edge_kernel(const int* __restrict__ nb_idx,
                                 const int* __restrict__ nb_k,
                                 const float* __restrict__ importance, int E) {
    int e = blockIdx.x * blockDim.x + threadIdx.x;
    if (e >= E) return;
    int ni = nb_idx[e];
    int kk = nb_k[e];
    g_edge[e] = make_int2(ni | (kk << 18), __float_as_int(importance[ni]));
}

// ---------------------------------------------------------------------------
// Main fused kernel. 256 threads = 8 warps; each group = 8 outputs.
// Phase 1: warp-per-output, 8-deep prefetched edge pipeline, f32x2 bins.
// Phase 2: register-hoisted W (36 regs/thread), o-paired f32x2 epilogue.
// ---------------------------------------------------------------------------
__global__ __launch_bounds__(256)
void sparse_conv_main(const float* __restrict__ feats,
                      const float* __restrict__ b_a,
                      const float* __restrict__ b_b,
                      float*       __restrict__ out) {
    // Rows padded to 12 floats (48B): 8B-aligned LDS.64 pairs, broadcast reads.
    __shared__ float Ta[JTOT][12];      // Sa[j][o]
    __shared__ float Tb[JTOT][12];      // Sb[j][o]
    __shared__ float Psm[8][C_OUT][9];  // partials [o][f][slice] (9-pad: no conflicts)
    __shared__ float impsm[8];

    const int tid  = threadIdx.x;
    const int w    = tid >> 5;          // warp id: output-in-group AND j-slice
    const int lane = tid & 31;          // channel (phase 1) / feature f (phase 2)
    const int f    = lane;

    const float bias = (f < C_A) ? b_a[f] : b_b[f - C_A];

    // Hoist this thread's W slice: Wt[w*36 + jj][f], loaded once, reused always.
    float Wreg[JSLICE];
    #pragma unroll
    for (int jj = 0; jj < JSLICE; jj++)
        Wreg[jj] = g_Wt[w * JSLICE + jj][f];

    const float* Ssel = (f < C_A) ? &Ta[0][0] : &Tb[0][0];

    for (int g = blockIdx.x; g < GROUPS; g += gridDim.x) {
        // =================== Phase 1: scatter-accumulate ===================
        const int n  = g * 8 + w;
        const int e0 = g_row_start[n];
        const int e1 = g_row_start[n + 1];

        ull acc[KBINS];                 // (Sa, Sb) packed per bin
        #pragma unroll
        for (int q = 0; q < KBINS; q++) acc[q] = 0ull;
        float isum_l = 0.f;

        for (int base = e0; base < e1; base += 32) {
            const int e = base + lane;
            int2 ed = (e < e1) ? g_edge[e] : make_int2(15 << 18, 0); // k=15: masked
            const float ii_l = __int_as_float(ed.y);
            isum_l += ii_l;

            const int nval    = min(32, e1 - base);
            const int ngroups = (nval + 7) >> 3;
            for (int gi = 0; gi < ngroups; gi++) {
                const int b8 = gi * 8;
                int   p[8];
                float iw[8];
                #pragma unroll
                for (int u = 0; u < 8; u++) {
                    p[u]  = __shfl_sync(0xffffffffu, ed.x, b8 + u);
                    iw[u] = __shfl_sync(0xffffffffu, ii_l, b8 + u);
                }
                float v[8];
                #pragma unroll
                for (int u = 0; u < 8; u++)   // 8 LDGs in flight (L2-hot, 128B lines)
                    v[u] = feats[(p[u] & 0x3FFFF) * C_IN + lane];
                #pragma unroll
                for (int u = 0; u < 8; u++) {
                    const int kq = p[u] >> 18;       // 15 for masked lanes
                    const ull m  = pack2(v[u], v[u] * iw[u]);
                    #pragma unroll
                    for (int q = 0; q < KBINS; q++)
                        if (kq == q) acc[q] = add2(acc[q], m);
                }
            }
        }

        // Stage S: row j = q*32+lane, column o = w.
        #pragma unroll
        for (int q = 0; q < KBINS; q++) {
            float sa, sb; unpack2(acc[q], sa, sb);
            Ta[q * 32 + lane][w] = sa;
            Tb[q * 32 + lane][w] = sb;
        }
        // Warp-reduce importance sum (lane-private partials).
        #pragma unroll
        for (int d = 16; d > 0; d >>= 1)
            isum_l += __shfl_xor_sync(0xffffffffu, isum_l, d);
        if (lane == 0) impsm[w] = isum_l;
        __syncthreads();

        // =================== Phase 2: epilogue GEMM ===================
        // thread (f, slice w): 36 j's, 8 outputs as 4 f32x2 pairs.
        ull a01 = 0ull, a23 = 0ull, a45 = 0ull, a67 = 0ull;
        #pragma unroll
        for (int jj = 0; jj < JSLICE; jj++) {
            const int j = w * JSLICE + jj;
            const ull* rp = (const ull*)(Ssel + j * 12);   // broadcast LDS.64 x4
            const ull  w2 = pack2(Wreg[jj], Wreg[jj]);
            a01 = fma2(rp[0], w2, a01);
            a23 = fma2(rp[1], w2, a23);
            a45 = fma2(rp[2], w2, a45);
            a67 = fma2(rp[3], w2, a67);
        }
        {
            float x, y;
            unpack2(a01, x, y); Psm[0][f][w] = x; Psm[1][f][w] = y;
            unpack2(a23, x, y); Psm[2][f][w] = x; Psm[3][f][w] = y;
            unpack2(a45, x, y); Psm[4][f][w] = x; Psm[5][f][w] = y;
            unpack2(a67, x, y); Psm[6][f][w] = x; Psm[7][f][w] = y;
        }
        __syncthreads();

        // Final reduce: thread (o = w, f) sums 8 slice-partials + epilogue.
        {
            const int n2 = g * 8 + w;
            float s = 0.f;
            #pragma unroll
            for (int sl = 0; sl < 8; sl++) s += Psm[w][f][sl];
            const float iv    = impsm[w];
            const float denom = (iv > 0.f) ? iv : 1.f;
            float r = (f < C_A) ? (s + bias) : (s / denom + bias);
            out[n2 * C_OUT + f] = fmaxf(r, 0.f);
            if (f == 0) out[N_OUT * C_OUT + n2] = iv;      // out_imp
        }
        __syncthreads();   // protect Ta/Tb before next group's phase 1
    }
}

// ---------------------------------------------------------------------------
extern "C" void kernel_launch(void* const* d_in, const int* in_sizes, int n_in,
                              void* d_out, int out_size) {
    const float* feats      = (const float*)d_in[0];
    const float* importance = (const float*)d_in[1];
    const float* W_a        = (const float*)d_in[2];
    const float* b_a        = (const float*)d_in[3];
    const float* W_b        = (const float*)d_in[4];
    const float* b_b        = (const float*)d_in[5];
    const int*   nb_idx     = (const int*)d_in[6];
    const int*   nb_k       = (const int*)d_in[7];
    const int*   nb_out     = (const int*)d_in[8];
    const int E = in_sizes[6];

    prep_wt_kernel<<<(JTOT * C_OUT + 255) / 256, 256>>>(W_a, W_b);
    prep_rows_kernel<<<(N_OUT + 1 + 255) / 256, 256>>>(nb_out, E);
    prep_edge_kernel<<<(E + 255) / 256, 256>>>(nb_idx, nb_k, importance, E);
    sparse_conv_main<<<1480, 256>>>(feats, b_a, b_b, (float*)d_out);
}

// round 3
// speedup vs baseline: 1.0383x; 1.0383x over previous
#include <cuda_runtime.h>

#define N_OUT   100000
#define KBINS   9
#define C_IN    32
#define C_A     24
#define C_B     8
#define C_OUT   32
#define JTOT    (KBINS * C_IN)      // 288
#define JSLICE  (JTOT / 8)          // 36
#define GROUPS  (N_OUT / 8)         // 12500 (exact)
#define E_MAX   1600000
#define PAD     12

typedef unsigned long long ull;

// ---- f32x2 packed helpers (sm_100+) ---------------------------------------
__device__ __forceinline__ ull pack2(float x, float y) {
    ull r; asm("mov.b64 %0, {%1, %2};" : "=l"(r) : "f"(x), "f"(y)); return r;
}
__device__ __forceinline__ void unpack2(ull v, float &x, float &y) {
    asm("mov.b64 {%0, %1}, %2;" : "=f"(x), "=f"(y) : "l"(v));
}
__device__ __forceinline__ ull add2(ull a, ull b) {
    ull r; asm("add.rn.f32x2 %0, %1, %2;" : "=l"(r) : "l"(a), "l"(b)); return r;
}
__device__ __forceinline__ ull fma2(ull a, ull b, ull c) {
    ull r; asm("fma.rn.f32x2 %0, %1, %2, %3;" : "=l"(r) : "l"(a), "l"(b), "l"(c)); return r;
}

// ---- device scratch --------------------------------------------------------
__device__ float g_Wt[JTOT][C_OUT];       // Wt[j][f], j = k*32+c
__device__ int   g_row_start[N_OUT + 1];  // CSR offsets
__device__ int2  g_edge[E_MAX];           // (ni*32 | k<<23, bitcast importance)

// ---------------------------------------------------------------------------
__global__ void prep_wt_kernel(const float* __restrict__ W_a,
                               const float* __restrict__ W_b) {
    int idx = blockIdx.x * blockDim.x + threadIdx.x;
    if (idx >= JTOT * C_OUT) return;
    int j = idx / C_OUT, f = idx % C_OUT;
    int k = j / C_IN,  c = j % C_IN;
    float w = (f < C_A) ? W_a[(k * C_IN + c) * C_A + f]
                        : W_b[(k * C_IN + c) * C_B + (f - C_A)];
    g_Wt[j][f] = w;
}

__global__ void prep_rows_kernel(const int* __restrict__ out_idx, int E) {
    int n = blockIdx.x * blockDim.x + threadIdx.x;
    if (n > N_OUT) return;
    int lo = 0, hi = E;
    while (lo < hi) {
        int mid = (lo + hi) >> 1;
        if (out_idx[mid] < n) lo = mid + 1; else hi = mid;
    }
    g_row_start[n] = lo;
}

__global__ void prep_edge_kernel(const int* __restrict__ nb_idx,
                                 const int* __restrict__ nb_k,
                                 const float* __restrict__ importance, int E) {
    int e = blockIdx.x * blockDim.x + threadIdx.x;
    if (e >= E) return;
    int ni = nb_idx[e];
    int kk = nb_k[e];
    // low 23 bits: ni*32 (pre-scaled feats row offset); bits [23:27): kernel bin
    g_edge[e] = make_int2((ni * C_IN) | (kk << 23), __float_as_int(importance[ni]));
}

// ---------------------------------------------------------------------------
// Main fused kernel. 256 threads = 8 warps; each group = 8 outputs.
// Phase 1: warp-per-output; bins in dynamically-indexed LOCAL array
//          (LDL/STL RMW, 4 slots/edge instead of 18 predicated ops).
// Phase 2: T[sel][j][12] staged; 2 LDS.128 + 4 FFMA2 per j; Wreg hoisted.
// ---------------------------------------------------------------------------
__global__ __launch_bounds__(256)
void sparse_conv_main(const float* __restrict__ feats,
                      const float* __restrict__ b_a,
                      const float* __restrict__ b_b,
                      float*       __restrict__ out) {
    __shared__ float T[2][JTOT][PAD];      // [a/b][j][o-pad12] : 27.6KB
    __shared__ float Psm[8][C_OUT][9];     // partials [o][f][slice] : 9.2KB
    __shared__ float impsm[8];

    const int tid  = threadIdx.x;
    const int w    = tid >> 5;
    const int lane = tid & 31;
    const int f    = lane;

    const float bias = (f < C_A) ? b_a[f] : b_b[f - C_A];

    // Per-thread W slice (loaded once; L2/L1-hot g_Wt).
    float Wreg[JSLICE];
    #pragma unroll
    for (int jj = 0; jj < JSLICE; jj++)
        Wreg[jj] = g_Wt[w * JSLICE + jj][f];

    const float* Sbase = &T[(f < C_A) ? 0 : 1][0][0];

    for (int g = blockIdx.x; g < GROUPS; g += gridDim.x) {
        // =================== Phase 1: scatter-accumulate ===================
        const int n  = g * 8 + w;
        const int e0 = g_row_start[n];
        const int e1 = g_row_start[n + 1];

        ull accL[KBINS];                // dynamic index -> local memory (L1)
        #pragma unroll
        for (int q = 0; q < KBINS; q++) accL[q] = 0ull;
        float isum = 0.f;               // identical on all lanes (uniform meta)

        int e = e0;
        for (; e + 4 <= e1; e += 4) {   // 4-deep pipeline: 4 ed + 4 v in flight
            const int2 E0 = g_edge[e + 0];
            const int2 E1 = g_edge[e + 1];
            const int2 E2 = g_edge[e + 2];
            const int2 E3 = g_edge[e + 3];
            const float v0 = __ldg(&feats[(E0.x & 0x7FFFFF) + lane]);
            const float v1 = __ldg(&feats[(E1.x & 0x7FFFFF) + lane]);
            const float v2 = __ldg(&feats[(E2.x & 0x7FFFFF) + lane]);
            const float v3 = __ldg(&feats[(E3.x & 0x7FFFFF) + lane]);
            {
                const float ii = __int_as_float(E0.y); isum += ii;
                const int kq = ((unsigned)E0.x) >> 23;
                accL[kq] = add2(accL[kq], pack2(v0, v0 * ii));
            }
            {
                const float ii = __int_as_float(E1.y); isum += ii;
                const int kq = ((unsigned)E1.x) >> 23;
                accL[kq] = add2(accL[kq], pack2(v1, v1 * ii));
            }
            {
                const float ii = __int_as_float(E2.y); isum += ii;
                const int kq = ((unsigned)E2.x) >> 23;
                accL[kq] = add2(accL[kq], pack2(v2, v2 * ii));
            }
            {
                const float ii = __int_as_float(E3.y); isum += ii;
                const int kq = ((unsigned)E3.x) >> 23;
                accL[kq] = add2(accL[kq], pack2(v3, v3 * ii));
            }
        }
        for (; e < e1; ++e) {           // tail
            const int2 E = g_edge[e];
            const float v = __ldg(&feats[(E.x & 0x7FFFFF) + lane]);
            const float ii = __int_as_float(E.y); isum += ii;
            const int kq = ((unsigned)E.x) >> 23;
            accL[kq] = add2(accL[kq], pack2(v, v * ii));
        }

        // Stage transposed: T[0/1][q*32+lane][w]
        #pragma unroll
        for (int q = 0; q < KBINS; q++) {
            float sa, sb; unpack2(accL[q], sa, sb);
            T[0][q * 32 + lane][w] = sa;
            T[1][q * 32 + lane][w] = sb;
        }
        if (lane == 0) impsm[w] = isum;
        __syncthreads();   // barrier A

        // =================== Phase 2: epilogue GEMM ===================
        // thread (f, slice w): 36 j's, 8 outputs as 4 f32x2 o-pairs.
        ull a01 = 0ull, a23 = 0ull, a45 = 0ull, a67 = 0ull;
        #pragma unroll
        for (int jj = 0; jj < JSLICE; jj++) {
            const int j = w * JSLICE + jj;
            const ull* rp = (const ull*)(Sbase + j * PAD);  // 16B-aligned rows
            const ull  w2 = pack2(Wreg[jj], Wreg[jj]);
            a01 = fma2(rp[0], w2, a01);   // LDS.128 -> (o0,o1),(o2,o3)
            a23 = fma2(rp[1], w2, a23);
            a45 = fma2(rp[2], w2, a45);   // LDS.128 -> (o4,o5),(o6,o7)
            a67 = fma2(rp[3], w2, a67);
        }
        {
            float x, y;
            unpack2(a01, x, y); Psm[0][f][w] = x; Psm[1][f][w] = y;
            unpack2(a23, x, y); Psm[2][f][w] = x; Psm[3][f][w] = y;
            unpack2(a45, x, y); Psm[4][f][w] = x; Psm[5][f][w] = y;
            unpack2(a67, x, y); Psm[6][f][w] = x; Psm[7][f][w] = y;
        }
        __syncthreads();   // barrier B (also protects T for next group's staging)

        // Final reduce + epilogue: thread (o = w, f).
        {
            const int n2 = g * 8 + w;
            float s = 0.f;
            #pragma unroll
            for (int sl = 0; sl < 8; sl++) s += Psm[w][f][sl];
            const float iv    = impsm[w];
            const float denom = (iv > 0.f) ? iv : 1.f;
            float r = (f < C_A) ? (s + bias) : (s / denom + bias);
            out[n2 * C_OUT + f] = fmaxf(r, 0.f);
            if (f == 0) out[N_OUT * C_OUT + n2] = iv;   // out_imp
        }
        // No barrier needed: next group touches only local acc until staging,
        // and staging is ordered behind barrier B; impsm/Psm slots are
        // per-warp-owned across the boundary.
    }
}

// ---------------------------------------------------------------------------
extern "C" void kernel_launch(void* const* d_in, const int* in_sizes, int n_in,
                              void* d_out, int out_size) {
    const float* feats      = (const float*)d_in[0];
    const float* importance = (const float*)d_in[1];
    const float* W_a        = (const float*)d_in[2];
    const float* b_a        = (const float*)d_in[3];
    const float* W_b        = (const float*)d_in[4];
    const float* b_b        = (const float*)d_in[5];
    const int*   nb_idx     = (const int*)d_in[6];
    const int*   nb_k       = (const int*)d_in[7];
    const int*   nb_out     = (const int*)d_in[8];
    const int E = in_sizes[6];

    prep_wt_kernel<<<(JTOT * C_OUT + 255) / 256, 256>>>(W_a, W_b);
    prep_rows_kernel<<<(N_OUT + 1 + 255) / 256, 256>>>(nb_out, E);
    prep_edge_kernel<<<(E + 255) / 256, 256>>>(nb_idx, nb_k, importance, E);
    sparse_conv_main<<<1480, 256>>>(feats, b_a, b_b, (float*)d_out);
}

// round 5
// speedup vs baseline: 1.3634x; 1.3131x over previous
#include <cuda_runtime.h>

#define N_OUT   100000
#define KBINS   9
#define C_IN    32
#define C_A     24
#define C_B     8
#define C_OUT   32
#define JTOT    (KBINS * C_IN)      // 288
#define JSLICE  (JTOT / 8)          // 36
#define GROUPS  (N_OUT / 8)         // 12500 (exact)
#define E_MAX   1600000
#define PAD     12                  // 48B rows: 16B-aligned for LDS.128

typedef unsigned long long ull;

// ---- f32x2 packed helpers (sm_100+) ---------------------------------------
__device__ __forceinline__ ull pack2(float x, float y) {
    ull r; asm("mov.b64 %0, {%1, %2};" : "=l"(r) : "f"(x), "f"(y)); return r;
}
__device__ __forceinline__ void unpack2(ull v, float &x, float &y) {
    asm("mov.b64 {%0, %1}, %2;" : "=f"(x), "=f"(y) : "l"(v));
}
__device__ __forceinline__ ull add2(ull a, ull b) {
    ull r; asm("add.rn.f32x2 %0, %1, %2;" : "=l"(r) : "l"(a), "l"(b)); return r;
}
__device__ __forceinline__ ull fma2(ull a, ull b, ull c) {
    ull r; asm("fma.rn.f32x2 %0, %1, %2, %3;" : "=l"(r) : "l"(a), "l"(b), "l"(c)); return r;
}

// ---- device scratch --------------------------------------------------------
__device__ float g_Wt[JTOT][C_OUT];       // Wt[j][f], j = k*32+c
__device__ int   g_row_start[N_OUT + 1];  // CSR offsets
__device__ int2  g_edge[E_MAX];           // SORTED by (out, bin): (ni*32|bin<<23, imp)

// ---------------------------------------------------------------------------
__global__ void prep_wt_kernel(const float* __restrict__ W_a,
                               const float* __restrict__ W_b) {
    int idx = blockIdx.x * blockDim.x + threadIdx.x;
    if (idx >= JTOT * C_OUT) return;
    int j = idx / C_OUT, f = idx % C_OUT;
    int k = j / C_IN,  c = j % C_IN;
    float w = (f < C_A) ? W_a[(k * C_IN + c) * C_A + f]
                        : W_b[(k * C_IN + c) * C_B + (f - C_A)];
    g_Wt[j][f] = w;
}

__global__ void prep_rows_kernel(const int* __restrict__ out_idx, int E) {
    int n = blockIdx.x * blockDim.x + threadIdx.x;
    if (n > N_OUT) return;
    int lo = 0, hi = E;
    while (lo < hi) {
        int mid = (lo + hi) >> 1;
        if (out_idx[mid] < n) lo = mid + 1; else hi = mid;
    }
    g_row_start[n] = lo;
}

// Warp-per-output counting sort by bin (edges already grouped by output).
// Pass 1: 9-ballot histogram. Prefix. Pass 2: rank-and-scatter packed meta.
__global__ void sort_edges_kernel(const int* __restrict__ nb_idx,
                                  const int* __restrict__ nb_k,
                                  const float* __restrict__ importance) {
    const int wid  = (blockIdx.x * blockDim.x + threadIdx.x) >> 5;
    const int lane = threadIdx.x & 31;
    if (wid >= N_OUT) return;
    const int e0 = g_row_start[wid], e1 = g_row_start[wid + 1];
    if (e0 == e1) return;
    const unsigned lt = (1u << lane) - 1u;

    int h[KBINS];
    #pragma unroll
    for (int q = 0; q < KBINS; q++) h[q] = 0;
    for (int base = e0; base < e1; base += 32) {
        const int e = base + lane;
        const int k = (e < e1) ? nb_k[e] : -1;
        #pragma unroll
        for (int q = 0; q < KBINS; q++)
            h[q] += __popc(__ballot_sync(0xffffffffu, k == q));
    }
    int off[KBINS];
    off[0] = 0;
    #pragma unroll
    for (int q = 1; q < KBINS; q++) off[q] = off[q - 1] + h[q - 1];

    for (int base = e0; base < e1; base += 32) {
        const int e = base + lane;
        const bool valid = e < e1;
        const int k = valid ? nb_k[e] : -1;
        unsigned bal[KBINS];
        #pragma unroll
        for (int q = 0; q < KBINS; q++)
            bal[q] = __ballot_sync(0xffffffffu, k == q);
        int pos = 0;
        #pragma unroll
        for (int q = 0; q < KBINS; q++)
            if (k == q) pos = off[q] + __popc(bal[q] & lt);
        if (valid) {
            const int ni = nb_idx[e];
            g_edge[e0 + pos] = make_int2((ni * C_IN) | (k << 23),
                                         __float_as_int(importance[ni]));
        }
        #pragma unroll
        for (int q = 0; q < KBINS; q++) off[q] += __popc(bal[q]);
    }
}

// ---------------------------------------------------------------------------
// Main fused kernel. 256 threads = 8 warps; group = 8 outputs.
// Phase 1: sorted edges -> single running (Sa,Sb) f32x2 accumulator,
//          flushed to smem T on (uniform) bin change. No predication/RMW.
// Phase 2: 2 LDS.128 + 4 FFMA2 per j, Wreg hoisted, slice-reduced via Psm.
// ---------------------------------------------------------------------------
__global__ __launch_bounds__(256, 4)
void sparse_conv_main(const float* __restrict__ feats,
                      const float* __restrict__ b_a,
                      const float* __restrict__ b_b,
                      float*       __restrict__ out) {
    __shared__ float T[2][JTOT][PAD];      // 27.6KB
    __shared__ float Psm[8][C_OUT][9];     // 9.2KB
    __shared__ float impsm[8];

    const int tid  = threadIdx.x;
    const int w    = tid >> 5;
    const int lane = tid & 31;
    const int f    = lane;

    const float bias = (f < C_A) ? b_a[f] : b_b[f - C_A];

    float Wreg[JSLICE];
    #pragma unroll
    for (int jj = 0; jj < JSLICE; jj++)
        Wreg[jj] = g_Wt[w * JSLICE + jj][f];

    const float* Sbase = &T[(f < C_A) ? 0 : 1][0][0];
    float* const t0 = &T[0][0][0] + lane * PAD + w;     // column w, row lane
    float* const t1 = t0 + JTOT * PAD;                  // T[1] mirror

#define UPDATE(ED, V) do {                                        \
        const int nb_ = ((unsigned)(ED).x) >> 23;                 \
        if (nb_ != cur) {                                         \
            float sa_, sb_; unpack2(run, sa_, sb_);               \
            t0[cur * (32 * PAD)] = sa_;                           \
            t1[cur * (32 * PAD)] = sb_;                           \
            touched |= (1u << cur); run = 0ull; cur = nb_;        \
        }                                                         \
        const float ii_ = __int_as_float((ED).y); isum += ii_;    \
        run = add2(run, pack2((V), (V) * ii_));                   \
    } while (0)

    for (int g = blockIdx.x; g < GROUPS; g += gridDim.x) {
        // =================== Phase 1 ===================
        const int n  = g * 8 + w;
        const int e0 = g_row_start[n];
        const int e1 = g_row_start[n + 1];

        ull run = 0ull; int cur = 0; unsigned touched = 0u; float isum = 0.f;

        int e = e0;
        for (; e + 4 <= e1; e += 4) {       // 4-deep meta+feats prefetch
            const int2 A = g_edge[e + 0];
            const int2 B = g_edge[e + 1];
            const int2 C = g_edge[e + 2];
            const int2 D = g_edge[e + 3];
            const float v0 = __ldg(&feats[(A.x & 0x7FFFFF) + lane]);
            const float v1 = __ldg(&feats[(B.x & 0x7FFFFF) + lane]);
            const float v2 = __ldg(&feats[(C.x & 0x7FFFFF) + lane]);
            const float v3 = __ldg(&feats[(D.x & 0x7FFFFF) + lane]);
            UPDATE(A, v0); UPDATE(B, v1); UPDATE(C, v2); UPDATE(D, v3);
        }
        for (; e < e1; ++e) {
            const int2 A = g_edge[e];
            const float v = __ldg(&feats[(A.x & 0x7FFFFF) + lane]);
            UPDATE(A, v);
        }
        if (e1 > e0) {                      // final flush
            float sa, sb; unpack2(run, sa, sb);
            t0[cur * (32 * PAD)] = sa;
            t1[cur * (32 * PAD)] = sb;
            touched |= (1u << cur);
        }
        #pragma unroll
        for (int q = 0; q < KBINS; q++)     // zero-fill untouched bins
            if (!((touched >> q) & 1u)) {
                t0[q * (32 * PAD)] = 0.f;
                t1[q * (32 * PAD)] = 0.f;
            }
        if (lane == 0) impsm[w] = isum;     // isum is warp-uniform
        __syncthreads();   // barrier A

        // =================== Phase 2 ===================
        ull a01 = 0ull, a23 = 0ull, a45 = 0ull, a67 = 0ull;
        #pragma unroll
        for (int jj = 0; jj < JSLICE; jj++) {
            const int j = w * JSLICE + jj;
            const ull* rp = (const ull*)(Sbase + j * PAD);
            const ull  w2 = pack2(Wreg[jj], Wreg[jj]);
            a01 = fma2(rp[0], w2, a01);
            a23 = fma2(rp[1], w2, a23);
            a45 = fma2(rp[2], w2, a45);
            a67 = fma2(rp[3], w2, a67);
        }
        {
            float x, y;
            unpack2(a01, x, y); Psm[0][f][w] = x; Psm[1][f][w] = y;
            unpack2(a23, x, y); Psm[2][f][w] = x; Psm[3][f][w] = y;
            unpack2(a45, x, y); Psm[4][f][w] = x; Psm[5][f][w] = y;
            unpack2(a67, x, y); Psm[6][f][w] = x; Psm[7][f][w] = y;
        }
        __syncthreads();   // barrier B

        {
            const int n2 = g * 8 + w;
            float s = 0.f;
            #pragma unroll
            for (int sl = 0; sl < 8; sl++) s += Psm[w][f][sl];
            const float iv    = impsm[w];
            const float denom = (iv > 0.f) ? iv : 1.f;
            float r = (f < C_A) ? (s + bias) : (s / denom + bias);
            out[n2 * C_OUT + f] = fmaxf(r, 0.f);
            if (f == 0) out[N_OUT * C_OUT + n2] = iv;
        }
        // Next group's T writes are safe: all T reads precede barrier B.
    }
#undef UPDATE
}

// ---------------------------------------------------------------------------
extern "C" void kernel_launch(void* const* d_in, const int* in_sizes, int n_in,
                              void* d_out, int out_size) {
    const float* feats      = (const float*)d_in[0];
    const float* importance = (const float*)d_in[1];
    const float* W_a        = (const float*)d_in[2];
    const float* b_a        = (const float*)d_in[3];
    const float* W_b        = (const float*)d_in[4];
    const float* b_b        = (const float*)d_in[5];
    const int*   nb_idx     = (const int*)d_in[6];
    const int*   nb_k       = (const int*)d_in[7];
    const int*   nb_out     = (const int*)d_in[8];
    const int E = in_sizes[6];

    prep_wt_kernel<<<(JTOT * C_OUT + 255) / 256, 256>>>(W_a, W_b);
    prep_rows_kernel<<<(N_OUT + 1 + 255) / 256, 256>>>(nb_out, E);
    sort_edges_kernel<<<(N_OUT * 32 + 255) / 256, 256>>>(nb_idx, nb_k, importance);
    sparse_conv_main<<<592, 256>>>(feats, b_a, b_b, (float*)d_out);
}

// round 6
// speedup vs baseline: 1.4183x; 1.0402x over previous
#include <cuda_runtime.h>

#define N_OUT   100000
#define KBINS   9
#define C_IN    32
#define C_A     24
#define C_B     8
#define C_OUT   32
#define JTOT    (KBINS * C_IN)      // 288
#define JSLICE  (JTOT / 8)          // 36
#define GROUPS  (N_OUT / 8)         // 12500 (exact)
#define E_MAX   1600000

typedef unsigned long long ull;

// ---- f32x2 packed helpers (sm_100+) ---------------------------------------
__device__ __forceinline__ ull pack2(float x, float y) {
    ull r; asm("mov.b64 %0, {%1, %2};" : "=l"(r) : "f"(x), "f"(y)); return r;
}
__device__ __forceinline__ void unpack2(ull v, float &x, float &y) {
    asm("mov.b64 {%0, %1}, %2;" : "=f"(x), "=f"(y) : "l"(v));
}
__device__ __forceinline__ ull add2(ull a, ull b) {
    ull r; asm("add.rn.f32x2 %0, %1, %2;" : "=l"(r) : "l"(a), "l"(b)); return r;
}

// ---- device scratch --------------------------------------------------------
__device__ float g_Wt[JTOT][C_OUT];       // Wt[j][f], j = k*32+c
__device__ int   g_row_start[N_OUT + 1];  // CSR offsets
__device__ int2  g_edge[E_MAX];           // SORTED by (out, bin): (ni*32|bin<<23, imp)

// ---------------------------------------------------------------------------
__global__ void prep_wt_kernel(const float* __restrict__ W_a,
                               const float* __restrict__ W_b) {
    int idx = blockIdx.x * blockDim.x + threadIdx.x;
    if (idx >= JTOT * C_OUT) return;
    int j = idx / C_OUT, f = idx % C_OUT;
    int k = j / C_IN,  c = j % C_IN;
    float w = (f < C_A) ? W_a[(k * C_IN + c) * C_A + f]
                        : W_b[(k * C_IN + c) * C_B + (f - C_A)];
    g_Wt[j][f] = w;
}

__global__ void prep_rows_kernel(const int* __restrict__ out_idx, int E) {
    int n = blockIdx.x * blockDim.x + threadIdx.x;
    if (n > N_OUT) return;
    int lo = 0, hi = E;
    while (lo < hi) {
        int mid = (lo + hi) >> 1;
        if (out_idx[mid] < n) lo = mid + 1; else hi = mid;
    }
    g_row_start[n] = lo;
}

// Warp-per-output counting sort by bin (edges already grouped by output).
__global__ void sort_edges_kernel(const int* __restrict__ nb_idx,
                                  const int* __restrict__ nb_k,
                                  const float* __restrict__ importance) {
    const int wid  = (blockIdx.x * blockDim.x + threadIdx.x) >> 5;
    const int lane = threadIdx.x & 31;
    if (wid >= N_OUT) return;
    const int e0 = g_row_start[wid], e1 = g_row_start[wid + 1];
    if (e0 == e1) return;
    const unsigned lt = (1u << lane) - 1u;

    int h[KBINS];
    #pragma unroll
    for (int q = 0; q < KBINS; q++) h[q] = 0;
    for (int base = e0; base < e1; base += 32) {
        const int e = base + lane;
        const int k = (e < e1) ? nb_k[e] : -1;
        #pragma unroll
        for (int q = 0; q < KBINS; q++)
            h[q] += __popc(__ballot_sync(0xffffffffu, k == q));
    }
    int off[KBINS];
    off[0] = 0;
    #pragma unroll
    for (int q = 1; q < KBINS; q++) off[q] = off[q - 1] + h[q - 1];

    for (int base = e0; base < e1; base += 32) {
        const int e = base + lane;
        const bool valid = e < e1;
        const int k = valid ? nb_k[e] : -1;
        unsigned bal[KBINS];
        #pragma unroll
        for (int q = 0; q < KBINS; q++)
            bal[q] = __ballot_sync(0xffffffffu, k == q);
        int pos = 0;
        #pragma unroll
        for (int q = 0; q < KBINS; q++)
            if (k == q) pos = off[q] + __popc(bal[q] & lt);
        if (valid) {
            const int ni = nb_idx[e];
            g_edge[e0 + pos] = make_int2((ni * C_IN) | (k << 23),
                                         __float_as_int(importance[ni]));
        }
        #pragma unroll
        for (int q = 0; q < KBINS; q++) off[q] += __popc(bal[q]);
    }
}

// ---------------------------------------------------------------------------
// Main fused kernel. 256 threads = 8 warps; group = 8 outputs.
// T transposed to [branch][o][288]: flush/zero STS contiguous (1 phase),
// phase-2 reads contiguous float4 broadcast. Edge meta via int4 (2 edges/LDG).
// ---------------------------------------------------------------------------
__global__ __launch_bounds__(256, 4)
void sparse_conv_main(const float* __restrict__ feats,
                      const float* __restrict__ b_a,
                      const float* __restrict__ b_b,
                      float*       __restrict__ out) {
    __shared__ float T[2][8][JTOT];        // 18.4KB, rows 16B-aligned
    __shared__ float Psm[8][C_OUT][9];     // 9.2KB, conflict-free (stride 9)
    __shared__ float impsm[8];

    const int tid  = threadIdx.x;
    const int w    = tid >> 5;
    const int lane = tid & 31;
    const int f    = lane;

    const float bias = (f < C_A) ? b_a[f] : b_b[f - C_A];

    // Per-thread W slice (scalar; 36 regs).
    float Wreg[JSLICE];
    #pragma unroll
    for (int jj = 0; jj < JSLICE; jj++)
        Wreg[jj] = g_Wt[w * JSLICE + jj][f];

    const float* Sbase = &T[(f < C_A) ? 0 : 1][0][0];
    float* const t0 = &T[0][w][lane];      // branch-a row of output w
    float* const t1 = &T[1][w][lane];

#define UPDATE(EX, EY, V) do {                                    \
        const int nb_ = ((unsigned)(EX)) >> 23;                   \
        if (nb_ != cur) {                                         \
            float sa_, sb_; unpack2(run, sa_, sb_);               \
            t0[cur * 32] = sa_;                                   \
            t1[cur * 32] = sb_;                                   \
            touched |= (1u << cur); run = 0ull; cur = nb_;        \
        }                                                         \
        const float ii_ = __int_as_float(EY); isum += ii_;        \
        run = add2(run, pack2((V), (V) * ii_));                   \
    } while (0)

    for (int g = blockIdx.x; g < GROUPS; g += gridDim.x) {
        // =================== Phase 1 ===================
        const int n  = g * 8 + w;
        const int e0 = g_row_start[n];
        const int e1 = g_row_start[n + 1];

        ull run = 0ull; int cur = 0; unsigned touched = 0u; float isum = 0.f;

        int e = e0;
        if ((e & 1) && e < e1) {            // align to even index for int4
            const int2 A = g_edge[e];
            const float v = __ldg(&feats[(A.x & 0x7FFFFF) + lane]);
            UPDATE(A.x, A.y, v);
            ++e;
        }
        for (; e + 4 <= e1; e += 4) {       // 2 LDG.128 meta + 4 feats in flight
            const int4 P = *(const int4*)&g_edge[e];
            const int4 Q = *(const int4*)&g_edge[e + 2];
            const float v0 = __ldg(&feats[(P.x & 0x7FFFFF) + lane]);
            const float v1 = __ldg(&feats[(P.z & 0x7FFFFF) + lane]);
            const float v2 = __ldg(&feats[(Q.x & 0x7FFFFF) + lane]);
            const float v3 = __ldg(&feats[(Q.z & 0x7FFFFF) + lane]);
            UPDATE(P.x, P.y, v0); UPDATE(P.z, P.w, v1);
            UPDATE(Q.x, Q.y, v2); UPDATE(Q.z, Q.w, v3);
        }
        if (e + 2 <= e1) {
            const int4 P = *(const int4*)&g_edge[e];
            const float v0 = __ldg(&feats[(P.x & 0x7FFFFF) + lane]);
            const float v1 = __ldg(&feats[(P.z & 0x7FFFFF) + lane]);
            UPDATE(P.x, P.y, v0); UPDATE(P.z, P.w, v1);
            e += 2;
        }
        if (e < e1) {
            const int2 A = g_edge[e];
            const float v = __ldg(&feats[(A.x & 0x7FFFFF) + lane]);
            UPDATE(A.x, A.y, v);
        }
        if (e1 > e0) {                      // final flush
            float sa, sb; unpack2(run, sa, sb);
            t0[cur * 32] = sa;
            t1[cur * 32] = sb;
            touched |= (1u << cur);
        }
        #pragma unroll
        for (int q = 0; q < KBINS; q++)     // zero untouched bins (contiguous)
            if (!((touched >> q) & 1u)) {
                t0[q * 32] = 0.f;
                t1[q * 32] = 0.f;
            }
        if (lane == 0) impsm[w] = isum;     // warp-uniform
        __syncthreads();   // barrier A

        // =================== Phase 2 ===================
        // thread (f, slice w): for each output o, 9 broadcast float4 reads
        // over the 36-j slice, 36 scalar FFMAs.
        float acc[8];
        const int jbase = w * JSLICE;
        #pragma unroll
        for (int o = 0; o < 8; o++) {
            const float4* sp = (const float4*)(Sbase + o * JTOT + jbase);
            float a = 0.f;
            #pragma unroll
            for (int t = 0; t < JSLICE / 4; t++) {      // 9 LDS.128
                const float4 s4 = sp[t];
                a = fmaf(s4.x, Wreg[4 * t + 0], a);
                a = fmaf(s4.y, Wreg[4 * t + 1], a);
                a = fmaf(s4.z, Wreg[4 * t + 2], a);
                a = fmaf(s4.w, Wreg[4 * t + 3], a);
            }
            acc[o] = a;
        }
        #pragma unroll
        for (int o = 0; o < 8; o++)
            Psm[o][f][w] = acc[o];
        __syncthreads();   // barrier B (also protects T for next group)

        {
            const int n2 = g * 8 + w;
            float s = 0.f;
            #pragma unroll
            for (int sl = 0; sl < 8; sl++) s += Psm[w][f][sl];
            const float iv    = impsm[w];
            const float denom = (iv > 0.f) ? iv : 1.f;
            float r = (f < C_A) ? (s + bias) : (s / denom + bias);
            out[n2 * C_OUT + f] = fmaxf(r, 0.f);
            if (f == 0) out[N_OUT * C_OUT + n2] = iv;
        }
        // Next group's T writes are ordered behind barrier B.
    }
#undef UPDATE
}

// ---------------------------------------------------------------------------
extern "C" void kernel_launch(void* const* d_in, const int* in_sizes, int n_in,
                              void* d_out, int out_size) {
    const float* feats      = (const float*)d_in[0];
    const float* importance = (const float*)d_in[1];
    const float* W_a        = (const float*)d_in[2];
    const float* b_a        = (const float*)d_in[3];
    const float* W_b        = (const float*)d_in[4];
    const float* b_b        = (const float*)d_in[5];
    const int*   nb_idx     = (const int*)d_in[6];
    const int*   nb_k       = (const int*)d_in[7];
    const int*   nb_out     = (const int*)d_in[8];
    const int E = in_sizes[6];

    prep_wt_kernel<<<(JTOT * C_OUT + 255) / 256, 256>>>(W_a, W_b);
    prep_rows_kernel<<<(N_OUT + 1 + 255) / 256, 256>>>(nb_out, E);
    sort_edges_kernel<<<(N_OUT * 32 + 255) / 256, 256>>>(nb_idx, nb_k, importance);
    sparse_conv_main<<<592, 256>>>(feats, b_a, b_b, (float*)d_out);
}

// round 7
// speedup vs baseline: 1.5295x; 1.0784x over previous
#include <cuda_runtime.h>

#define N_OUT   100000
#define KBINS   9
#define C_IN    32
#define C_A     24
#define C_B     8
#define C_OUT   32
#define JTOT    (KBINS * C_IN)      // 288
#define GROUPS  (N_OUT / 8)         // 12500
#define E_MAX   1600000

// Phase-2 team geometry: 16 teams x 16 lanes; slice = 18 j per team.
#define TSLICE  18
#define NTEAMS  16
// T layout: [branch][o][R] floats, branch offset BOFF.
#define R       292                 // even, R%32=4
#define BOFF    2344                // 8*292 + 8 ; BOFF%32 = 8
#define PSTR    35                  // Psm team-row stride (odd -> conflict-free)

typedef unsigned long long ull;

__device__ __forceinline__ ull pack2(float x, float y) {
    ull r; asm("mov.b64 %0, {%1, %2};" : "=l"(r) : "f"(x), "f"(y)); return r;
}
__device__ __forceinline__ void unpack2(ull v, float &x, float &y) {
    asm("mov.b64 {%0, %1}, %2;" : "=f"(x), "=f"(y) : "l"(v));
}
__device__ __forceinline__ ull add2(ull a, ull b) {
    ull r; asm("add.rn.f32x2 %0, %1, %2;" : "=l"(r) : "l"(a), "l"(b)); return r;
}

// ---- device scratch --------------------------------------------------------
__device__ float g_Wt[JTOT][C_OUT];       // Wt[j][f], j = k*32+c
__device__ int   g_row_start[N_OUT + 1];
__device__ __align__(16) int2 g_edge[E_MAX];  // sorted by (out, bin)

// ---------------------------------------------------------------------------
__global__ void prep_wt_kernel(const float* __restrict__ W_a,
                               const float* __restrict__ W_b) {
    int idx = blockIdx.x * blockDim.x + threadIdx.x;
    if (idx >= JTOT * C_OUT) return;
    int j = idx / C_OUT, f = idx % C_OUT;
    int k = j / C_IN,  c = j % C_IN;
    float w = (f < C_A) ? W_a[(k * C_IN + c) * C_A + f]
                        : W_b[(k * C_IN + c) * C_B + (f - C_A)];
    g_Wt[j][f] = w;
}

__global__ void prep_rows_kernel(const int* __restrict__ out_idx, int E) {
    int n = blockIdx.x * blockDim.x + threadIdx.x;
    if (n > N_OUT) return;
    int lo = 0, hi = E;
    while (lo < hi) {
        int mid = (lo + hi) >> 1;
        if (out_idx[mid] < n) lo = mid + 1; else hi = mid;
    }
    g_row_start[n] = lo;
}

// Warp-per-output counting sort by bin.
__global__ void sort_edges_kernel(const int* __restrict__ nb_idx,
                                  const int* __restrict__ nb_k,
                                  const float* __restrict__ importance) {
    const int wid  = (blockIdx.x * blockDim.x + threadIdx.x) >> 5;
    const int lane = threadIdx.x & 31;
    if (wid >= N_OUT) return;
    const int e0 = g_row_start[wid], e1 = g_row_start[wid + 1];
    if (e0 == e1) return;
    const unsigned lt = (1u << lane) - 1u;

    int h[KBINS];
    #pragma unroll
    for (int q = 0; q < KBINS; q++) h[q] = 0;
    for (int base = e0; base < e1; base += 32) {
        const int e = base + lane;
        const int k = (e < e1) ? nb_k[e] : -1;
        #pragma unroll
        for (int q = 0; q < KBINS; q++)
            h[q] += __popc(__ballot_sync(0xffffffffu, k == q));
    }
    int off[KBINS];
    off[0] = 0;
    #pragma unroll
    for (int q = 1; q < KBINS; q++) off[q] = off[q - 1] + h[q - 1];

    for (int base = e0; base < e1; base += 32) {
        const int e = base + lane;
        const bool valid = e < e1;
        const int k = valid ? nb_k[e] : -1;
        unsigned bal[KBINS];
        #pragma unroll
        for (int q = 0; q < KBINS; q++)
            bal[q] = __ballot_sync(0xffffffffu, k == q);
        int pos = 0;
        #pragma unroll
        for (int q = 0; q < KBINS; q++)
            if (k == q) pos = off[q] + __popc(bal[q] & lt);
        if (valid) {
            const int ni = nb_idx[e];
            g_edge[e0 + pos] = make_int2((ni * C_IN) | (k << 23),
                                         __float_as_int(importance[ni]));
        }
        #pragma unroll
        for (int q = 0; q < KBINS; q++) off[q] += __popc(bal[q]);
    }
}

// ---------------------------------------------------------------------------
// Main fused kernel. 256 threads = 8 warps; group = 8 outputs.
// Phase 1: warp-per-output, sorted-bin running accumulator -> T rows.
// Phase 2: 16 teams x 16 lanes; lane owns features (2l,2l+1): each S float
//          read feeds 2 FMAs -> S writeback halves. W pairs in 36 regs.
// ---------------------------------------------------------------------------
__global__ __launch_bounds__(256, 3)
void sparse_conv_main(const float* __restrict__ feats,
                      const float* __restrict__ b_a,
                      const float* __restrict__ b_b,
                      float*       __restrict__ out) {
    __shared__ float T[2 * BOFF];             // Ta at 0, Tb at BOFF   (18.8KB)
    __shared__ float PS[8 * NTEAMS * PSTR];   // partials [o][team][35] (17.9KB)
    __shared__ float impsm[8];

    const int tid  = threadIdx.x;
    const int w    = tid >> 5;          // warp id: phase-1 output, reduce output
    const int lane = tid & 31;          // phase-1 channel, reduce feature
    const int team = tid >> 4;          // phase-2 team (0..15): j-slice
    const int tl   = tid & 15;          // phase-2 lane: features (2tl, 2tl+1)

    const float bias = (lane < C_A) ? b_a[lane] : b_b[lane - C_A];

    // W pairs for this thread: (W[j][2tl], W[j][2tl+1]) for j in team slice.
    float2 Wp[TSLICE];
    #pragma unroll
    for (int jj = 0; jj < TSLICE; jj++)
        Wp[jj] = *(const float2*)&g_Wt[team * TSLICE + jj][2 * tl];

    // Phase-2 S base for this lane: branch by feature pair, plus slice offset.
    const float* Tlane = T + ((2 * tl < C_A) ? 0 : BOFF) + team * TSLICE;

    float* const t0 = T + w * R + lane;         // phase-1 flush targets
    float* const t1 = t0 + BOFF;

#define UPDATE(EX, EY, V) do {                                    \
        const int nb_ = ((unsigned)(EX)) >> 23;                   \
        if (nb_ != cur) {                                         \
            float sa_, sb_; unpack2(run, sa_, sb_);               \
            t0[cur * 32] = sa_;                                   \
            t1[cur * 32] = sb_;                                   \
            touched |= (1u << cur); run = 0ull; cur = nb_;        \
        }                                                         \
        const float ii_ = __int_as_float(EY); isum += ii_;        \
        run = add2(run, pack2((V), (V) * ii_));                   \
    } while (0)

    for (int g = blockIdx.x; g < GROUPS; g += gridDim.x) {
        // =================== Phase 1 ===================
        const int n  = g * 8 + w;
        const int e0 = g_row_start[n];
        const int e1 = g_row_start[n + 1];

        ull run = 0ull; int cur = 0; unsigned touched = 0u; float isum = 0.f;

        int e = e0;
        if ((e & 1) && e < e1) {
            const int2 A = g_edge[e];
            const float v = __ldg(&feats[(A.x & 0x7FFFFF) + lane]);
            UPDATE(A.x, A.y, v);
            ++e;
        }
        for (; e + 4 <= e1; e += 4) {
            const int4 P = *(const int4*)&g_edge[e];
            const int4 Q = *(const int4*)&g_edge[e + 2];
            const float v0 = __ldg(&feats[(P.x & 0x7FFFFF) + lane]);
            const float v1 = __ldg(&feats[(P.z & 0x7FFFFF) + lane]);
            const float v2 = __ldg(&feats[(Q.x & 0x7FFFFF) + lane]);
            const float v3 = __ldg(&feats[(Q.z & 0x7FFFFF) + lane]);
            UPDATE(P.x, P.y, v0); UPDATE(P.z, P.w, v1);
            UPDATE(Q.x, Q.y, v2); UPDATE(Q.z, Q.w, v3);
        }
        if (e + 2 <= e1) {
            const int4 P = *(const int4*)&g_edge[e];
            const float v0 = __ldg(&feats[(P.x & 0x7FFFFF) + lane]);
            const float v1 = __ldg(&feats[(P.z & 0x7FFFFF) + lane]);
            UPDATE(P.x, P.y, v0); UPDATE(P.z, P.w, v1);
            e += 2;
        }
        if (e < e1) {
            const int2 A = g_edge[e];
            const float v = __ldg(&feats[(A.x & 0x7FFFFF) + lane]);
            UPDATE(A.x, A.y, v);
        }
        if (e1 > e0) {
            float sa, sb; unpack2(run, sa, sb);
            t0[cur * 32] = sa;
            t1[cur * 32] = sb;
            touched |= (1u << cur);
        }
        #pragma unroll
        for (int q = 0; q < KBINS; q++)
            if (!((touched >> q) & 1u)) {
                t0[q * 32] = 0.f;
                t1[q * 32] = 0.f;
            }
        if (lane == 0) impsm[w] = isum;
        __syncthreads();   // barrier A

        // =================== Phase 2: team GEMM ===================
        // For each output o: 9 LDS.64 over the 18-j slice; each S float
        // feeds 2 FMAs (features 2tl, 2tl+1).
        #pragma unroll
        for (int o = 0; o < 8; o++) {
            const float2* sp = (const float2*)(Tlane + o * R);
            float ax = 0.f, ay = 0.f;
            #pragma unroll
            for (int jp = 0; jp < TSLICE / 2; jp++) {
                const float2 s = sp[jp];
                ax = fmaf(s.x, Wp[2 * jp].x, ax);
                ay = fmaf(s.x, Wp[2 * jp].y, ay);
                ax = fmaf(s.y, Wp[2 * jp + 1].x, ax);
                ay = fmaf(s.y, Wp[2 * jp + 1].y, ay);
            }
            PS[(o * NTEAMS + team) * PSTR + 2 * tl]     = ax;
            PS[(o * NTEAMS + team) * PSTR + 2 * tl + 1] = ay;
        }
        __syncthreads();   // barrier B

        // =================== Reduce + epilogue: warp w -> output w ===================
        {
            const int n2 = g * 8 + w;
            const float* pr = PS + (w * NTEAMS) * PSTR + lane;
            // balanced tree over 16 team partials
            float s0 = pr[0 * PSTR] + pr[1 * PSTR];
            float s1 = pr[2 * PSTR] + pr[3 * PSTR];
            float s2 = pr[4 * PSTR] + pr[5 * PSTR];
            float s3 = pr[6 * PSTR] + pr[7 * PSTR];
            float s4 = pr[8 * PSTR] + pr[9 * PSTR];
            float s5 = pr[10 * PSTR] + pr[11 * PSTR];
            float s6 = pr[12 * PSTR] + pr[13 * PSTR];
            float s7 = pr[14 * PSTR] + pr[15 * PSTR];
            float s = ((s0 + s1) + (s2 + s3)) + ((s4 + s5) + (s6 + s7));
            const float iv    = impsm[w];
            const float denom = (iv > 0.f) ? iv : 1.f;
            float r = (lane < C_A) ? (s + bias) : (s / denom + bias);
            out[n2 * C_OUT + lane] = fmaxf(r, 0.f);
            if (lane == 0) out[N_OUT * C_OUT + n2] = iv;
        }
        // Hazards: next group's T/PS writes happen after barrier A of the next
        // iteration; all reads of this group's T precede barrier B, and PS
        // reads precede the next barrier A. Safe with two barriers.
    }
#undef UPDATE
}

// ---------------------------------------------------------------------------
extern "C" void kernel_launch(void* const* d_in, const int* in_sizes, int n_in,
                              void* d_out, int out_size) {
    const float* feats      = (const float*)d_in[0];
    const float* importance = (const float*)d_in[1];
    const float* W_a        = (const float*)d_in[2];
    const float* b_a        = (const float*)d_in[3];
    const float* W_b        = (const float*)d_in[4];
    const float* b_b        = (const float*)d_in[5];
    const int*   nb_idx     = (const int*)d_in[6];
    const int*   nb_k       = (const int*)d_in[7];
    const int*   nb_out     = (const int*)d_in[8];
    const int E = in_sizes[6];

    prep_wt_kernel<<<(JTOT * C_OUT + 255) / 256, 256>>>(W_a, W_b);
    prep_rows_kernel<<<(N_OUT + 1 + 255) / 256, 256>>>(nb_out, E);
    sort_edges_kernel<<<(N_OUT * 32 + 255) / 256, 256>>>(nb_idx, nb_k, importance);
    sparse_conv_main<<<444, 256>>>(feats, b_a, b_b, (float*)d_out);
}